// round 15
// baseline (speedup 1.0000x reference)
#include <cuda_runtime.h>
#include <cuda_bf16.h>
#include <cstdint>

#define NB 4
#define NS 2048
#define ND 1024
#define NH 16
#define DH 64
#define N3 3072
#define MROWS (NB * NS)  // 8192

// Device scratch (allocation-free)
__device__ __nv_bfloat16 g_ahi[(size_t)MROWS * ND];
__device__ __nv_bfloat16 g_alo[(size_t)MROWS * ND];
__device__ __nv_bfloat16 g_wthi[(size_t)N3 * ND];   // W^T hi [3072,1024]
__device__ __nv_bfloat16 g_wtlo[(size_t)N3 * ND];
__device__ __nv_bfloat16 g_qh[(size_t)NB * NH * NS * DH];   // Q hi [B,H,S,Dh]
__device__ __nv_bfloat16 g_kh[(size_t)NB * NH * NS * DH];   // K hi [B,H,S,Dh]
__device__ __nv_bfloat16 g_kl[(size_t)NB * NH * NS * DH];
__device__ __nv_bfloat16 g_vth[(size_t)NB * NH * DH * NS];  // V^T hi [B,H,Dh,S]

// ---------------------------------------------------------------------------
// helpers
// ---------------------------------------------------------------------------
__device__ __forceinline__ uint32_t smem_u32(const void* p) {
    uint32_t a;
    asm("{ .reg .u64 t; cvta.to.shared.u64 t, %1; cvt.u32.u64 %0, t; }"
        : "=r"(a) : "l"(p));
    return a;
}
#define CP_ASYNC16(dst, src) \
    asm volatile("cp.async.cg.shared.global [%0], [%1], 16;" :: "r"(dst), "l"(src))
#define CP_COMMIT() asm volatile("cp.async.commit_group;" ::: "memory")
#define CP_WAIT(n)  asm volatile("cp.async.wait_group %0;" :: "n"(n) : "memory")
#define LDSM4(r, addr) asm volatile( \
    "ldmatrix.sync.aligned.m8n8.x4.shared.b16 {%0,%1,%2,%3}, [%4];" \
    : "=r"((r)[0]), "=r"((r)[1]), "=r"((r)[2]), "=r"((r)[3]) : "r"(addr))
#define MMA_BF16(c, a, b0, b1) asm volatile( \
    "mma.sync.aligned.m16n8k16.row.col.f32.bf16.bf16.f32 " \
    "{%0,%1,%2,%3}, {%4,%5,%6,%7}, {%8,%9}, {%0,%1,%2,%3};" \
    : "+f"((c)[0]), "+f"((c)[1]), "+f"((c)[2]), "+f"((c)[3]) \
    : "r"((a)[0]), "r"((a)[1]), "r"((a)[2]), "r"((a)[3]), "r"(b0), "r"(b1))

__device__ __forceinline__ uint32_t packbf2(float a, float b) {
    __nv_bfloat162 t = __floats2bfloat162_rn(a, b);
    return *reinterpret_cast<uint32_t*>(&t);
}
// Truncated-hi pack: 1 PRMT. Exactly compensated by the lo term below.
__device__ __forceinline__ uint32_t pack_hi_tr(float a, float b) {
    return __byte_perm(__float_as_uint(a), __float_as_uint(b), 0x7632);
}
// Residual vs truncated hi: exact FADD (low mantissa bits), then rn pack.
__device__ __forceinline__ uint32_t pack_lo_tr(float a, float b) {
    float ha = __uint_as_float(__float_as_uint(a) & 0xFFFF0000u);
    float hb = __uint_as_float(__float_as_uint(b) & 0xFFFF0000u);
    return packbf2(a - ha, b - hb);
}

// ---------------------------------------------------------------------------
// Prekernel: split A (fp32 -> bf16 hi + lo)
// ---------------------------------------------------------------------------
__global__ __launch_bounds__(256) void split_a_kernel(const float* __restrict__ A) {
    size_t i = ((size_t)blockIdx.x * 256 + threadIdx.x) * 4;
    float4 v = *(const float4*)(A + i);
    __nv_bfloat162 h01 = __floats2bfloat162_rn(v.x, v.y);
    __nv_bfloat162 h23 = __floats2bfloat162_rn(v.z, v.w);
    __nv_bfloat162 l01 = __floats2bfloat162_rn(v.x - __bfloat162float(h01.x),
                                               v.y - __bfloat162float(h01.y));
    __nv_bfloat162 l23 = __floats2bfloat162_rn(v.z - __bfloat162float(h23.x),
                                               v.w - __bfloat162float(h23.y));
    *(__nv_bfloat162*)(g_ahi + i)     = h01;
    *(__nv_bfloat162*)(g_ahi + i + 2) = h23;
    *(__nv_bfloat162*)(g_alo + i)     = l01;
    *(__nv_bfloat162*)(g_alo + i + 2) = l23;
}

// ---------------------------------------------------------------------------
// Prekernel: split + transpose W [1024,3072] -> Wt hi/lo [3072,1024]
// ---------------------------------------------------------------------------
__global__ __launch_bounds__(256) void split_wt_kernel(const float* __restrict__ W) {
    __shared__ float t[32][33];
    const int n0 = blockIdx.x * 32, k0 = blockIdx.y * 32;
    const int tx = threadIdx.x, ty = threadIdx.y;  // 32 x 8
#pragma unroll
    for (int j = 0; j < 4; j++)
        t[ty + j * 8][tx] = W[(size_t)(k0 + ty + j * 8) * N3 + n0 + tx];
    __syncthreads();
#pragma unroll
    for (int j = 0; j < 4; j++) {
        int n = n0 + ty + j * 8, k = k0 + tx;
        float v = t[tx][ty + j * 8];
        __nv_bfloat16 h = __float2bfloat16_rn(v);
        g_wthi[(size_t)n * ND + k] = h;
        g_wtlo[(size_t)n * ND + k] = __float2bfloat16_rn(v - __bfloat162float(h));
    }
}

// ---------------------------------------------------------------------------
// QKV GEMM on HMMA. CTA 256x128 (BM=256 halves B reloads; LDGSTS-issue is the
// binder), 512 threads = 16 warps (8m x 2n; per-warp shape identical to R14).
// K/V tiles 3-term split; Q tiles 2-term (no A-lo). KC=32, double-buffered.
// ---------------------------------------------------------------------------
#define GST 40                      // bf16 smem stride
#define A_ARR_B (256 * GST * 2)     // 20480 B per A array
#define B_ARR_B (128 * GST * 2)     // 10240 B per B array
#define AH_OFF 0
#define AL_OFF A_ARR_B
#define BH_OFF (2 * A_ARR_B)
#define BL_OFF (2 * A_ARR_B + B_ARR_B)
#define STAGE_B (2 * A_ARR_B + 2 * B_ARR_B)   // 61440
#define TST 264                     // V transpose staging stride (halfwords)

__global__ __launch_bounds__(512, 1) void qkv_hmma_kernel(
    const float* __restrict__ bias, float* __restrict__ kout, float* __restrict__ vout)
{
    extern __shared__ char gsm[];
    __shared__ float sbias[128];
    const uint32_t sb0 = smem_u32(gsm);
    const int tid = threadIdx.x;
    const int wid = tid >> 5, lane = tid & 31;
    const int wm = wid >> 1, wn = wid & 1;   // wm 0..7, wn 0..1
    const int m0 = blockIdx.y * 256, n0 = blockIdx.x * 128;
    const bool qt = (n0 < ND);      // Q-tile: 2-term, no A-lo

    if (tid < 128) sbias[tid] = bias[n0 + tid];

    const __nv_bfloat16* gAh = g_ahi + (size_t)m0 * ND;
    const __nv_bfloat16* gAl = g_alo + (size_t)m0 * ND;
    const __nv_bfloat16* gBh = g_wthi + (size_t)n0 * ND;
    const __nv_bfloat16* gBl = g_wtlo + (size_t)n0 * ND;

    // loader coords: A rows r0g (0..127) and r0g+128; B rows r0g
    const int r0g = tid >> 2, c0g = (tid & 3) * 8;

    float acc[2][8][4];
#pragma unroll
    for (int mt = 0; mt < 2; mt++)
#pragma unroll
        for (int nt = 0; nt < 8; nt++)
#pragma unroll
            for (int e = 0; e < 4; e++) acc[mt][nt][e] = 0.0f;

    const int lrA = lane & 15, hkA = (lane >> 4) * 8;
    const int lrB = (lane & 7) + ((lane >> 4) & 1) * 8;
    const int hkB = ((lane >> 3) & 1) * 8;

#define LOAD_STAGE(kc, buf) do { \
    uint32_t d = sb0 + (buf) * STAGE_B; \
    size_t ga0 = (size_t)r0g * ND + (kc) * 32 + c0g; \
    size_t ga1 = (size_t)(r0g + 128) * ND + (kc) * 32 + c0g; \
    uint32_t s0 = (uint32_t)(r0g * GST + c0g) * 2; \
    uint32_t s1 = (uint32_t)((r0g + 128) * GST + c0g) * 2; \
    CP_ASYNC16(d + AH_OFF + s0, gAh + ga0); \
    CP_ASYNC16(d + AH_OFF + s1, gAh + ga1); \
    if (!qt) { \
        CP_ASYNC16(d + AL_OFF + s0, gAl + ga0); \
        CP_ASYNC16(d + AL_OFF + s1, gAl + ga1); \
    } \
    CP_ASYNC16(d + BH_OFF + s0, gBh + ga0); \
    CP_ASYNC16(d + BL_OFF + s0, gBl + ga0); \
} while (0)

    LOAD_STAGE(0, 0);
    CP_COMMIT();

    for (int kc = 0; kc < ND / 32; kc++) {
        const int buf = kc & 1;
        if (kc + 1 < ND / 32) {
            LOAD_STAGE(kc + 1, buf ^ 1);
            CP_COMMIT();
            CP_WAIT(1);
        } else {
            CP_WAIT(0);
        }
        __syncthreads();

        const uint32_t sbuf = sb0 + buf * STAGE_B;
#pragma unroll
        for (int kk = 0; kk < 2; kk++) {
            uint32_t ah[2][4], al[2][4];
#pragma unroll
            for (int mt = 0; mt < 2; mt++) {
                uint32_t a = sbuf +
                    (uint32_t)((wm * 32 + mt * 16 + lrA) * GST + kk * 16 + hkA) * 2;
                LDSM4(ah[mt], a + AH_OFF);
                if (!qt) LDSM4(al[mt], a + AL_OFF);
            }
#pragma unroll
            for (int nt2 = 0; nt2 < 4; nt2++) {
                uint32_t bh4[4], bl4[4];
                uint32_t a = sbuf +
                    (uint32_t)((wn * 64 + nt2 * 16 + lrB) * GST + kk * 16 + hkB) * 2;
                LDSM4(bh4, a + BH_OFF);
                LDSM4(bl4, a + BL_OFF);
#pragma unroll
                for (int mt = 0; mt < 2; mt++)
#pragma unroll
                    for (int half = 0; half < 2; half++) {
                        const int nt = nt2 * 2 + half;
                        MMA_BF16(acc[mt][nt], ah[mt], bh4[half * 2], bh4[half * 2 + 1]);
                        MMA_BF16(acc[mt][nt], ah[mt], bl4[half * 2], bl4[half * 2 + 1]);
                        if (!qt)
                            MMA_BF16(acc[mt][nt], al[mt], bh4[half * 2], bh4[half * 2 + 1]);
                    }
            }
        }
        __syncthreads();
    }

    // Epilogue
    const int sel = n0 >> 10;
    const int rl = lane >> 2, cpair = (lane & 3) * 2;
    __nv_bfloat16* T = (__nv_bfloat16*)gsm;  // transpose staging (sel==2 only)
#pragma unroll
    for (int mt = 0; mt < 2; mt++) {
#pragma unroll
        for (int half = 0; half < 2; half++) {
            const int mloc = wm * 32 + mt * 16 + rl + half * 8;
            const int m = m0 + mloc;
            const int b = m >> 11, s = m & (NS - 1);
#pragma unroll
            for (int nt = 0; nt < 8; nt++) {
                const int coln = wn * 64 + nt * 8 + cpair;
                const int h = ((n0 & (ND - 1)) >> 6) + (coln >> 6);
                const int d = coln & 63;
                const float v0 = acc[mt][nt][half * 2 + 0] + sbias[coln];
                const float v1 = acc[mt][nt][half * 2 + 1] + sbias[coln + 1];
                const size_t idx = (((size_t)b * NH + h) * NS + s) * DH + d;
                __nv_bfloat162 hh = __floats2bfloat162_rn(v0, v1);
                if (sel == 0) {
                    *(__nv_bfloat162*)&g_qh[idx] = hh;
                } else if (sel == 1) {
                    __nv_bfloat162 ll = __floats2bfloat162_rn(
                        v0 - __bfloat162float(hh.x), v1 - __bfloat162float(hh.y));
                    *(float2*)&kout[idx] = make_float2(v0, v1);
                    *(__nv_bfloat162*)&g_kh[idx] = hh;
                    *(__nv_bfloat162*)&g_kl[idx] = ll;
                } else {
                    *(float2*)&vout[idx] = make_float2(v0, v1);
                    T[coln * TST + mloc] = hh.x;
                    T[(coln + 1) * TST + mloc] = hh.y;
                }
            }
        }
    }
    if (sel == 2) {
        __syncthreads();  // CTA-uniform condition; legal
        const int b2 = m0 >> 11, s0g = m0 & (NS - 1);
        const int hb = (n0 & (ND - 1)) >> 6;
        // 128 n-rows x 256 m-cols = 4096 uint4, 8 per thread
#pragma unroll
        for (int p = 0; p < 8; p++) {
            const int idx = tid + p * 512;
            const int n = idx >> 5, c8 = (idx & 31) * 8;
            uint4 v = *(uint4*)&T[n * TST + c8];
            const int h2 = hb + (n >> 6);
            const int d = n & 63;
            *(uint4*)&g_vth[(((size_t)b2 * NH + h2) * DH + d) * NS + s0g + c8] = v;
        }
    }
}

// ---------------------------------------------------------------------------
// Flash attention on HMMA. FA2 register-P, register-Q (hi; 2-term QK^T),
// 2-term PV (Ph*Vh + Pl*Vh), cp.async double-buffered K/V, diag-specialized
// log2-domain softmax. Bq=Bk=64, 4 warps x 16 rows, 4 CTAs/SM. (Unchanged.)
// ---------------------------------------------------------------------------
#define AS 72                       // bf16 smem stride
#define KVARR_B (64 * AS * 2)       // 9216 B per array
#define ATT_SMEM_B (6 * KVARR_B + 512)

#define SOFTMAX_BLOCK(DIAGC) do { \
    _Pragma("unroll") \
    for (int hi = 0; hi < 2; hi++) { \
        const int row = q0 + w * 16 + rq + hi * 8; \
        float mx = -1e30f; \
        _Pragma("unroll") \
        for (int nt = 0; nt < 8; nt++) { \
            float v0 = fmaf(sacc[nt][hi * 2 + 0], scale2, \
                            fmaf(mrow[nt * 8 + cq], M2C, -M2C)); \
            float v1 = fmaf(sacc[nt][hi * 2 + 1], scale2, \
                            fmaf(mrow[nt * 8 + cq + 1], M2C, -M2C)); \
            if (DIAGC && (k0 + nt * 8 + cq + 0 > row)) v0 = -1e30f; \
            if (DIAGC && (k0 + nt * 8 + cq + 1 > row)) v1 = -1e30f; \
            sacc[nt][hi * 2 + 0] = v0; \
            sacc[nt][hi * 2 + 1] = v1; \
            mx = fmaxf(mx, fmaxf(v0, v1)); \
        } \
        mx = fmaxf(mx, __shfl_xor_sync(0xffffffffu, mx, 1)); \
        mx = fmaxf(mx, __shfl_xor_sync(0xffffffffu, mx, 2)); \
        const float mn = fmaxf(m2[hi], mx); \
        const float alpha = exp2f(m2[hi] - mn); \
        m2[hi] = mn; \
        float ps = 0.0f; \
        _Pragma("unroll") \
        for (int nt = 0; nt < 8; nt++) { \
            float p0 = exp2f(sacc[nt][hi * 2 + 0] - mn); \
            float p1 = exp2f(sacc[nt][hi * 2 + 1] - mn); \
            sacc[nt][hi * 2 + 0] = p0; \
            sacc[nt][hi * 2 + 1] = p1; \
            ps += p0 + p1; \
        } \
        ps += __shfl_xor_sync(0xffffffffu, ps, 1); \
        ps += __shfl_xor_sync(0xffffffffu, ps, 2); \
        l2[hi] = l2[hi] * alpha + ps; \
        _Pragma("unroll") \
        for (int nt = 0; nt < 8; nt++) { \
            oacc[nt][hi * 2 + 0] *= alpha; \
            oacc[nt][hi * 2 + 1] *= alpha; \
        } \
    } \
} while (0)

__global__ __launch_bounds__(128, 4) void attn_hmma_kernel(
    const float* __restrict__ mask, float* __restrict__ out)
{
    extern __shared__ __nv_bfloat16 sb[];
    float* mbuf = (float*)(sb + 6 * 64 * AS);  // raw mask, 2 x 64 floats

    const int tid = threadIdx.x;
    const int w = tid >> 5, lane = tid & 31;
    const int qi = (gridDim.x - 1) - blockIdx.x;  // long blocks first
    const int h = blockIdx.y, b = blockIdx.z;
    const int q0 = qi * 64;
    const size_t hoff = (((size_t)b * NH + h) * NS) * DH;
    const __nv_bfloat16* gQh = g_qh + hoff + (size_t)q0 * DH;
    const __nv_bfloat16* gKh = g_kh + hoff;
    const __nv_bfloat16* gKl = g_kl + hoff;
    const size_t voff = (((size_t)b * NH + h) * DH) * NS;
    const __nv_bfloat16* gVh = g_vth + voff;
    const float* mrow_g = mask + (size_t)b * NS;

    const uint32_t uS0 = smem_u32(sb);
    const uint32_t uMB = smem_u32(mbuf);

    const int lrA = lane & 15, hkA = (lane >> 4) * 8;
    const int lrB = (lane & 7) + ((lane >> 4) & 1) * 8;
    const int hkB = ((lane >> 3) & 1) * 8;
    const int rq = lane >> 2, cq = (lane & 3) * 2;

    const int pr = tid >> 3;            // base row (+16 per p)
    const int pc = (tid & 7);           // 16B line within 128B row

#define ATT_PREFETCH(k0_, s_) do { \
    uint32_t kb = uS0 + (uint32_t)(3 * (s_)) * KVARR_B; \
    _Pragma("unroll") \
    for (int p = 0; p < 4; p++) { \
        int r = pr + p * 16; \
        uint32_t off = (uint32_t)(r * AS + pc * 8) * 2; \
        CP_ASYNC16(kb + off,               gKh + (size_t)((k0_) + r) * DH + pc * 8); \
        CP_ASYNC16(kb + KVARR_B + off,     gKl + (size_t)((k0_) + r) * DH + pc * 8); \
        CP_ASYNC16(kb + 2 * KVARR_B + off, gVh + (size_t)r * NS + (k0_) + pc * 8); \
    } \
    if (tid < 16) CP_ASYNC16(uMB + (s_) * 256 + tid * 16, mrow_g + (k0_) + tid * 4); \
} while (0)

    ATT_PREFETCH(0, 0);
    CP_COMMIT();

    // Stage Q hi tile through the (currently idle) buf1 area; pull A-fragments
    // into registers once.
    {
        __nv_bfloat16* Qtmp = sb + 3 * 64 * AS;
#pragma unroll
        for (int p = 0; p < 4; p++) {
            int f = tid + p * 128;
            int r = f >> 3, ln = (f & 7) * 8;
            *(uint4*)&Qtmp[r * AS + ln] = *(const uint4*)&gQh[(size_t)r * DH + ln];
        }
    }
    __syncthreads();
    uint32_t qf[4][4];
    {
        const uint32_t uQtmp = uS0 + (uint32_t)(3 * KVARR_B);
#pragma unroll
        for (int kk = 0; kk < 4; kk++)
            LDSM4(qf[kk], uQtmp + (uint32_t)((w * 16 + lrA) * AS + kk * 16 + hkA) * 2);
    }

    float oacc[8][4];
#pragma unroll
    for (int nt = 0; nt < 8; nt++)
#pragma unroll
        for (int e = 0; e < 4; e++) oacc[nt][e] = 0.0f;
    float m2[2] = {-1e30f, -1e30f}, l2[2] = {0.0f, 0.0f};
    const float scale2 = 0.125f * 1.4426950408889634f;   // scale * log2(e)
    const float M2C = 10000.0f * 1.4426950408889634f;    // mask coeff in log2

    for (int kt = 0; kt <= qi; kt++) {
        const int k0 = kt * 64;
        const int buf = kt & 1;
        __syncthreads();
        if (kt < qi) {
            ATT_PREFETCH(k0 + 64, buf ^ 1);
            CP_COMMIT();
            CP_WAIT(1);
        } else {
            CP_WAIT(0);
        }
        __syncthreads();

        const uint32_t uKh = uS0 + (uint32_t)(3 * buf) * KVARR_B;
        const uint32_t uKl = uKh + KVARR_B;
        const uint32_t uVh = uKh + 2 * KVARR_B;
        const float* mrow = mbuf + buf * 64;

        // ---- S = Qh @ K^T (2-term: Qh*Kh + Qh*Kl) ----
        float sacc[8][4];
#pragma unroll
        for (int nt = 0; nt < 8; nt++)
#pragma unroll
            for (int e = 0; e < 4; e++) sacc[nt][e] = 0.0f;
#pragma unroll
        for (int kk = 0; kk < 4; kk++) {
#pragma unroll
            for (int t2 = 0; t2 < 4; t2++) {
                uint32_t bh4[4], bl4[4];
                const uint32_t boff =
                    (uint32_t)((t2 * 16 + lrB) * AS + kk * 16 + hkB) * 2;
                LDSM4(bh4, uKh + boff);
                LDSM4(bl4, uKl + boff);
#pragma unroll
                for (int half = 0; half < 2; half++) {
                    const int nt = t2 * 2 + half;
                    MMA_BF16(sacc[nt], qf[kk], bh4[half * 2], bh4[half * 2 + 1]);
                    MMA_BF16(sacc[nt], qf[kk], bl4[half * 2], bl4[half * 2 + 1]);
                }
            }
        }

        // ---- softmax on fragments (log2 domain, diag-specialized) ----
        if (kt == qi) {
            SOFTMAX_BLOCK(1);
        } else {
            SOFTMAX_BLOCK(0);
        }

        // ---- O += P @ Vh: 2-term (Ph + Pl), P packed from registers ----
#pragma unroll
        for (int kk = 0; kk < 4; kk++) {
            uint32_t pah[4], pal[4];
            pah[0] = pack_hi_tr(sacc[2 * kk + 0][0], sacc[2 * kk + 0][1]);
            pah[1] = pack_hi_tr(sacc[2 * kk + 0][2], sacc[2 * kk + 0][3]);
            pah[2] = pack_hi_tr(sacc[2 * kk + 1][0], sacc[2 * kk + 1][1]);
            pah[3] = pack_hi_tr(sacc[2 * kk + 1][2], sacc[2 * kk + 1][3]);
            pal[0] = pack_lo_tr(sacc[2 * kk + 0][0], sacc[2 * kk + 0][1]);
            pal[1] = pack_lo_tr(sacc[2 * kk + 0][2], sacc[2 * kk + 0][3]);
            pal[2] = pack_lo_tr(sacc[2 * kk + 1][0], sacc[2 * kk + 1][1]);
            pal[3] = pack_lo_tr(sacc[2 * kk + 1][2], sacc[2 * kk + 1][3]);
#pragma unroll
            for (int t2 = 0; t2 < 4; t2++) {
                uint32_t bh4[4];
                const uint32_t boff =
                    (uint32_t)((t2 * 16 + lrB) * AS + kk * 16 + hkB) * 2;
                LDSM4(bh4, uVh + boff);
#pragma unroll
                for (int half = 0; half < 2; half++) {
                    const int nt = t2 * 2 + half;
                    MMA_BF16(oacc[nt], pah, bh4[half * 2], bh4[half * 2 + 1]);
                    MMA_BF16(oacc[nt], pal, bh4[half * 2], bh4[half * 2 + 1]);
                }
            }
        }
    }

    // normalize + merge heads
#pragma unroll
    for (int hi = 0; hi < 2; hi++) {
        const int row = q0 + w * 16 + rq + hi * 8;
        const float inv = 1.0f / l2[hi];
        float* orow = out + ((size_t)b * NS + row) * ND + h * DH;
#pragma unroll
        for (int nt = 0; nt < 8; nt++) {
            float2 o = make_float2(oacc[nt][hi * 2 + 0] * inv,
                                   oacc[nt][hi * 2 + 1] * inv);
            *(float2*)&orow[nt * 8 + cq] = o;
        }
    }
}

extern "C" void kernel_launch(void* const* d_in, const int* in_sizes, int n_in,
                              void* d_out, int out_size) {
    const float* hs   = (const float*)d_in[0];  // [B,S,D]
    const float* mask = (const float*)d_in[1];  // [B,S]
    const float* w    = (const float*)d_in[2];  // [D,3D]
    const float* bias = (const float*)d_in[3];  // [3D]

    float* out = (float*)d_out;
    float* kout = out + (size_t)NB * NS * ND;        // present[0] = K
    float* vout = kout + (size_t)NB * NH * NS * DH;  // present[1] = V

    cudaFuncSetAttribute(qkv_hmma_kernel,
                         cudaFuncAttributeMaxDynamicSharedMemorySize, 2 * STAGE_B);
    cudaFuncSetAttribute(attn_hmma_kernel,
                         cudaFuncAttributeMaxDynamicSharedMemorySize, ATT_SMEM_B);

    // 1) bf16 hi/lo splits
    split_a_kernel<<<(MROWS * ND) / (256 * 4), 256>>>(hs);
    split_wt_kernel<<<dim3(N3 / 32, ND / 32), dim3(32, 8)>>>(w);
    // 2) HMMA QKV GEMM (BM=256, 512 threads; Q 2-term, K/V 3-term)
    qkv_hmma_kernel<<<dim3(N3 / 128, MROWS / 256), 512, 2 * STAGE_B>>>(
        bias, kout, vout);
    // 3) HMMA flash attention (unchanged)
    attn_hmma_kernel<<<dim3(NS / 64, NH, NB), 128, ATT_SMEM_B>>>(mask, out);
}

// round 16
// speedup vs baseline: 1.1032x; 1.1032x over previous
#include <cuda_runtime.h>
#include <cuda_bf16.h>
#include <cstdint>

#define NB 4
#define NS 2048
#define ND 1024
#define NH 16
#define DH 64
#define N3 3072
#define MROWS (NB * NS)  // 8192

// Device scratch (allocation-free)
__device__ __nv_bfloat16 g_ahi[(size_t)MROWS * ND];
__device__ __nv_bfloat16 g_alo[(size_t)MROWS * ND];
__device__ __nv_bfloat16 g_wthi[(size_t)N3 * ND];   // W^T hi [3072,1024]
__device__ __nv_bfloat16 g_wtlo[(size_t)N3 * ND];
__device__ __nv_bfloat16 g_qh[(size_t)NB * NH * NS * DH];   // Q hi [B,H,S,Dh]
__device__ __nv_bfloat16 g_kh[(size_t)NB * NH * NS * DH];   // K hi [B,H,S,Dh]
__device__ __nv_bfloat16 g_kl[(size_t)NB * NH * NS * DH];
__device__ __nv_bfloat16 g_vth[(size_t)NB * NH * DH * NS];  // V^T hi [B,H,Dh,S]

// ---------------------------------------------------------------------------
// helpers
// ---------------------------------------------------------------------------
__device__ __forceinline__ uint32_t smem_u32(const void* p) {
    uint32_t a;
    asm("{ .reg .u64 t; cvta.to.shared.u64 t, %1; cvt.u32.u64 %0, t; }"
        : "=r"(a) : "l"(p));
    return a;
}
#define CP_ASYNC16(dst, src) \
    asm volatile("cp.async.cg.shared.global [%0], [%1], 16;" :: "r"(dst), "l"(src))
#define CP_COMMIT() asm volatile("cp.async.commit_group;" ::: "memory")
#define CP_WAIT(n)  asm volatile("cp.async.wait_group %0;" :: "n"(n) : "memory")
#define LDSM4(r, addr) asm volatile( \
    "ldmatrix.sync.aligned.m8n8.x4.shared.b16 {%0,%1,%2,%3}, [%4];" \
    : "=r"((r)[0]), "=r"((r)[1]), "=r"((r)[2]), "=r"((r)[3]) : "r"(addr))
#define MMA_BF16(c, a, b0, b1) asm volatile( \
    "mma.sync.aligned.m16n8k16.row.col.f32.bf16.bf16.f32 " \
    "{%0,%1,%2,%3}, {%4,%5,%6,%7}, {%8,%9}, {%0,%1,%2,%3};" \
    : "+f"((c)[0]), "+f"((c)[1]), "+f"((c)[2]), "+f"((c)[3]) \
    : "r"((a)[0]), "r"((a)[1]), "r"((a)[2]), "r"((a)[3]), "r"(b0), "r"(b1))

__device__ __forceinline__ uint32_t packbf2(float a, float b) {
    __nv_bfloat162 t = __floats2bfloat162_rn(a, b);
    return *reinterpret_cast<uint32_t*>(&t);
}
// Truncated-hi pack: 1 PRMT. Exactly compensated by the lo term below.
__device__ __forceinline__ uint32_t pack_hi_tr(float a, float b) {
    return __byte_perm(__float_as_uint(a), __float_as_uint(b), 0x7632);
}
// Residual vs truncated hi: exact FADD (low mantissa bits), then rn pack.
__device__ __forceinline__ uint32_t pack_lo_tr(float a, float b) {
    float ha = __uint_as_float(__float_as_uint(a) & 0xFFFF0000u);
    float hb = __uint_as_float(__float_as_uint(b) & 0xFFFF0000u);
    return packbf2(a - ha, b - hb);
}

// ---------------------------------------------------------------------------
// Prekernel: split A (fp32 -> bf16 hi + lo)
// ---------------------------------------------------------------------------
__global__ __launch_bounds__(256) void split_a_kernel(const float* __restrict__ A) {
    size_t i = ((size_t)blockIdx.x * 256 + threadIdx.x) * 4;
    float4 v = *(const float4*)(A + i);
    __nv_bfloat162 h01 = __floats2bfloat162_rn(v.x, v.y);
    __nv_bfloat162 h23 = __floats2bfloat162_rn(v.z, v.w);
    __nv_bfloat162 l01 = __floats2bfloat162_rn(v.x - __bfloat162float(h01.x),
                                               v.y - __bfloat162float(h01.y));
    __nv_bfloat162 l23 = __floats2bfloat162_rn(v.z - __bfloat162float(h23.x),
                                               v.w - __bfloat162float(h23.y));
    *(__nv_bfloat162*)(g_ahi + i)     = h01;
    *(__nv_bfloat162*)(g_ahi + i + 2) = h23;
    *(__nv_bfloat162*)(g_alo + i)     = l01;
    *(__nv_bfloat162*)(g_alo + i + 2) = l23;
}

// ---------------------------------------------------------------------------
// Prekernel: split + transpose W [1024,3072] -> Wt hi/lo [3072,1024]
// ---------------------------------------------------------------------------
__global__ __launch_bounds__(256) void split_wt_kernel(const float* __restrict__ W) {
    __shared__ float t[32][33];
    const int n0 = blockIdx.x * 32, k0 = blockIdx.y * 32;
    const int tx = threadIdx.x, ty = threadIdx.y;  // 32 x 8
#pragma unroll
    for (int j = 0; j < 4; j++)
        t[ty + j * 8][tx] = W[(size_t)(k0 + ty + j * 8) * N3 + n0 + tx];
    __syncthreads();
#pragma unroll
    for (int j = 0; j < 4; j++) {
        int n = n0 + ty + j * 8, k = k0 + tx;
        float v = t[tx][ty + j * 8];
        __nv_bfloat16 h = __float2bfloat16_rn(v);
        g_wthi[(size_t)n * ND + k] = h;
        g_wtlo[(size_t)n * ND + k] = __float2bfloat16_rn(v - __bfloat162float(h));
    }
}

// ---------------------------------------------------------------------------
// QKV GEMM on HMMA. CTA 256x128, 512 threads = 16 warps (8m x 2n).
// 3-stage cp.async pipeline, ONE barrier per stage:
//   wait(1) -> syncthreads -> compute(kc) -> prefetch(kc+2)+commit.
// Buffer safety: prefetch kc+2 overwrites buf (kc-1)%3 whose readers
// (compute kc-1) all passed this stage's barrier. K/V tiles 3-term split;
// Q tiles 2-term (no A-lo).
// ---------------------------------------------------------------------------
#define GST 40                      // bf16 smem stride
#define A_ARR_B (256 * GST * 2)     // 20480 B per A array
#define B_ARR_B (128 * GST * 2)     // 10240 B per B array
#define AH_OFF 0
#define AL_OFF A_ARR_B
#define BH_OFF (2 * A_ARR_B)
#define BL_OFF (2 * A_ARR_B + B_ARR_B)
#define STAGE_B (2 * A_ARR_B + 2 * B_ARR_B)   // 61440
#define NSTAGE 3
#define GEMM_SMEM_B (NSTAGE * STAGE_B)        // 184320
#define TST 264                     // V transpose staging stride (halfwords)

__global__ __launch_bounds__(512, 1) void qkv_hmma_kernel(
    const float* __restrict__ bias, float* __restrict__ kout, float* __restrict__ vout)
{
    extern __shared__ char gsm[];
    __shared__ float sbias[128];
    const uint32_t sb0 = smem_u32(gsm);
    const int tid = threadIdx.x;
    const int wid = tid >> 5, lane = tid & 31;
    const int wm = wid >> 1, wn = wid & 1;   // wm 0..7, wn 0..1
    const int m0 = blockIdx.y * 256, n0 = blockIdx.x * 128;
    const bool qt = (n0 < ND);      // Q-tile: 2-term, no A-lo

    if (tid < 128) sbias[tid] = bias[n0 + tid];

    const __nv_bfloat16* gAh = g_ahi + (size_t)m0 * ND;
    const __nv_bfloat16* gAl = g_alo + (size_t)m0 * ND;
    const __nv_bfloat16* gBh = g_wthi + (size_t)n0 * ND;
    const __nv_bfloat16* gBl = g_wtlo + (size_t)n0 * ND;

    // loader coords: A rows r0g (0..127) and r0g+128; B rows r0g
    const int r0g = tid >> 2, c0g = (tid & 3) * 8;

    float acc[2][8][4];
#pragma unroll
    for (int mt = 0; mt < 2; mt++)
#pragma unroll
        for (int nt = 0; nt < 8; nt++)
#pragma unroll
            for (int e = 0; e < 4; e++) acc[mt][nt][e] = 0.0f;

    const int lrA = lane & 15, hkA = (lane >> 4) * 8;
    const int lrB = (lane & 7) + ((lane >> 4) & 1) * 8;
    const int hkB = ((lane >> 3) & 1) * 8;

#define LOAD_STAGE(kc, buf) do { \
    uint32_t d = sb0 + (buf) * STAGE_B; \
    size_t ga0 = (size_t)r0g * ND + (kc) * 32 + c0g; \
    size_t ga1 = (size_t)(r0g + 128) * ND + (kc) * 32 + c0g; \
    uint32_t s0 = (uint32_t)(r0g * GST + c0g) * 2; \
    uint32_t s1 = (uint32_t)((r0g + 128) * GST + c0g) * 2; \
    CP_ASYNC16(d + AH_OFF + s0, gAh + ga0); \
    CP_ASYNC16(d + AH_OFF + s1, gAh + ga1); \
    if (!qt) { \
        CP_ASYNC16(d + AL_OFF + s0, gAl + ga0); \
        CP_ASYNC16(d + AL_OFF + s1, gAl + ga1); \
    } \
    CP_ASYNC16(d + BH_OFF + s0, gBh + ga0); \
    CP_ASYNC16(d + BL_OFF + s0, gBl + ga0); \
} while (0)

    LOAD_STAGE(0, 0);
    CP_COMMIT();
    LOAD_STAGE(1, 1);
    CP_COMMIT();

    for (int kc = 0; kc < ND / 32; kc++) {
        if (kc < ND / 32 - 1) {
            CP_WAIT(1);   // group kc complete (kc+1 may be pending)
        } else {
            CP_WAIT(0);   // last stage: everything done
        }
        __syncthreads();  // cross-thread visibility + buffer-reuse fence

        const uint32_t sbuf = sb0 + (kc % 3) * STAGE_B;
#pragma unroll
        for (int kk = 0; kk < 2; kk++) {
            uint32_t ah[2][4], al[2][4];
#pragma unroll
            for (int mt = 0; mt < 2; mt++) {
                uint32_t a = sbuf +
                    (uint32_t)((wm * 32 + mt * 16 + lrA) * GST + kk * 16 + hkA) * 2;
                LDSM4(ah[mt], a + AH_OFF);
                if (!qt) LDSM4(al[mt], a + AL_OFF);
            }
#pragma unroll
            for (int nt2 = 0; nt2 < 4; nt2++) {
                uint32_t bh4[4], bl4[4];
                uint32_t a = sbuf +
                    (uint32_t)((wn * 64 + nt2 * 16 + lrB) * GST + kk * 16 + hkB) * 2;
                LDSM4(bh4, a + BH_OFF);
                LDSM4(bl4, a + BL_OFF);
#pragma unroll
                for (int mt = 0; mt < 2; mt++)
#pragma unroll
                    for (int half = 0; half < 2; half++) {
                        const int nt = nt2 * 2 + half;
                        MMA_BF16(acc[mt][nt], ah[mt], bh4[half * 2], bh4[half * 2 + 1]);
                        MMA_BF16(acc[mt][nt], ah[mt], bl4[half * 2], bl4[half * 2 + 1]);
                        if (!qt)
                            MMA_BF16(acc[mt][nt], al[mt], bh4[half * 2], bh4[half * 2 + 1]);
                    }
            }
        }

        // prefetch stage kc+2 into buf (kc+2)%3 (readers of that buf finished
        // compute kc-1 before this stage's barrier)
        if (kc + 2 < ND / 32) {
            LOAD_STAGE(kc + 2, (kc + 2) % 3);
            CP_COMMIT();
        }
    }

    // Epilogue
    const int sel = n0 >> 10;
    const int rl = lane >> 2, cpair = (lane & 3) * 2;
    __nv_bfloat16* T = (__nv_bfloat16*)gsm;  // transpose staging (sel==2 only)
    __syncthreads();  // all compute done before reusing gsm as staging
#pragma unroll
    for (int mt = 0; mt < 2; mt++) {
#pragma unroll
        for (int half = 0; half < 2; half++) {
            const int mloc = wm * 32 + mt * 16 + rl + half * 8;
            const int m = m0 + mloc;
            const int b = m >> 11, s = m & (NS - 1);
#pragma unroll
            for (int nt = 0; nt < 8; nt++) {
                const int coln = wn * 64 + nt * 8 + cpair;
                const int h = ((n0 & (ND - 1)) >> 6) + (coln >> 6);
                const int d = coln & 63;
                const float v0 = acc[mt][nt][half * 2 + 0] + sbias[coln];
                const float v1 = acc[mt][nt][half * 2 + 1] + sbias[coln + 1];
                const size_t idx = (((size_t)b * NH + h) * NS + s) * DH + d;
                __nv_bfloat162 hh = __floats2bfloat162_rn(v0, v1);
                if (sel == 0) {
                    *(__nv_bfloat162*)&g_qh[idx] = hh;
                } else if (sel == 1) {
                    __nv_bfloat162 ll = __floats2bfloat162_rn(
                        v0 - __bfloat162float(hh.x), v1 - __bfloat162float(hh.y));
                    *(float2*)&kout[idx] = make_float2(v0, v1);
                    *(__nv_bfloat162*)&g_kh[idx] = hh;
                    *(__nv_bfloat162*)&g_kl[idx] = ll;
                } else {
                    *(float2*)&vout[idx] = make_float2(v0, v1);
                    T[coln * TST + mloc] = hh.x;
                    T[(coln + 1) * TST + mloc] = hh.y;
                }
            }
        }
    }
    if (sel == 2) {
        __syncthreads();  // CTA-uniform condition; legal
        const int b2 = m0 >> 11, s0g = m0 & (NS - 1);
        const int hb = (n0 & (ND - 1)) >> 6;
        // 128 n-rows x 256 m-cols = 4096 uint4, 8 per thread
#pragma unroll
        for (int p = 0; p < 8; p++) {
            const int idx = tid + p * 512;
            const int n = idx >> 5, c8 = (idx & 31) * 8;
            uint4 v = *(uint4*)&T[n * TST + c8];
            const int h2 = hb + (n >> 6);
            const int d = n & 63;
            *(uint4*)&g_vth[(((size_t)b2 * NH + h2) * DH + d) * NS + s0g + c8] = v;
        }
    }
}

// ---------------------------------------------------------------------------
// Flash attention on HMMA. FA2 register-P, register-Q (hi; 2-term QK^T),
// 2-term PV (Ph*Vh + Pl*Vh), cp.async double-buffered K/V, diag-specialized
// log2-domain softmax. Bq=Bk=64, 4 warps x 16 rows, 4 CTAs/SM. (Unchanged.)
// ---------------------------------------------------------------------------
#define AS 72                       // bf16 smem stride
#define KVARR_B (64 * AS * 2)       // 9216 B per array
#define ATT_SMEM_B (6 * KVARR_B + 512)

#define SOFTMAX_BLOCK(DIAGC) do { \
    _Pragma("unroll") \
    for (int hi = 0; hi < 2; hi++) { \
        const int row = q0 + w * 16 + rq + hi * 8; \
        float mx = -1e30f; \
        _Pragma("unroll") \
        for (int nt = 0; nt < 8; nt++) { \
            float v0 = fmaf(sacc[nt][hi * 2 + 0], scale2, \
                            fmaf(mrow[nt * 8 + cq], M2C, -M2C)); \
            float v1 = fmaf(sacc[nt][hi * 2 + 1], scale2, \
                            fmaf(mrow[nt * 8 + cq + 1], M2C, -M2C)); \
            if (DIAGC && (k0 + nt * 8 + cq + 0 > row)) v0 = -1e30f; \
            if (DIAGC && (k0 + nt * 8 + cq + 1 > row)) v1 = -1e30f; \
            sacc[nt][hi * 2 + 0] = v0; \
            sacc[nt][hi * 2 + 1] = v1; \
            mx = fmaxf(mx, fmaxf(v0, v1)); \
        } \
        mx = fmaxf(mx, __shfl_xor_sync(0xffffffffu, mx, 1)); \
        mx = fmaxf(mx, __shfl_xor_sync(0xffffffffu, mx, 2)); \
        const float mn = fmaxf(m2[hi], mx); \
        const float alpha = exp2f(m2[hi] - mn); \
        m2[hi] = mn; \
        float ps = 0.0f; \
        _Pragma("unroll") \
        for (int nt = 0; nt < 8; nt++) { \
            float p0 = exp2f(sacc[nt][hi * 2 + 0] - mn); \
            float p1 = exp2f(sacc[nt][hi * 2 + 1] - mn); \
            sacc[nt][hi * 2 + 0] = p0; \
            sacc[nt][hi * 2 + 1] = p1; \
            ps += p0 + p1; \
        } \
        ps += __shfl_xor_sync(0xffffffffu, ps, 1); \
        ps += __shfl_xor_sync(0xffffffffu, ps, 2); \
        l2[hi] = l2[hi] * alpha + ps; \
        _Pragma("unroll") \
        for (int nt = 0; nt < 8; nt++) { \
            oacc[nt][hi * 2 + 0] *= alpha; \
            oacc[nt][hi * 2 + 1] *= alpha; \
        } \
    } \
} while (0)

__global__ __launch_bounds__(128, 4) void attn_hmma_kernel(
    const float* __restrict__ mask, float* __restrict__ out)
{
    extern __shared__ __nv_bfloat16 sb[];
    float* mbuf = (float*)(sb + 6 * 64 * AS);  // raw mask, 2 x 64 floats

    const int tid = threadIdx.x;
    const int w = tid >> 5, lane = tid & 31;
    const int qi = (gridDim.x - 1) - blockIdx.x;  // long blocks first
    const int h = blockIdx.y, b = blockIdx.z;
    const int q0 = qi * 64;
    const size_t hoff = (((size_t)b * NH + h) * NS) * DH;
    const __nv_bfloat16* gQh = g_qh + hoff + (size_t)q0 * DH;
    const __nv_bfloat16* gKh = g_kh + hoff;
    const __nv_bfloat16* gKl = g_kl + hoff;
    const size_t voff = (((size_t)b * NH + h) * DH) * NS;
    const __nv_bfloat16* gVh = g_vth + voff;
    const float* mrow_g = mask + (size_t)b * NS;

    const uint32_t uS0 = smem_u32(sb);
    const uint32_t uMB = smem_u32(mbuf);

    const int lrA = lane & 15, hkA = (lane >> 4) * 8;
    const int lrB = (lane & 7) + ((lane >> 4) & 1) * 8;
    const int hkB = ((lane >> 3) & 1) * 8;
    const int rq = lane >> 2, cq = (lane & 3) * 2;

    const int pr = tid >> 3;            // base row (+16 per p)
    const int pc = (tid & 7);           // 16B line within 128B row

#define ATT_PREFETCH(k0_, s_) do { \
    uint32_t kb = uS0 + (uint32_t)(3 * (s_)) * KVARR_B; \
    _Pragma("unroll") \
    for (int p = 0; p < 4; p++) { \
        int r = pr + p * 16; \
        uint32_t off = (uint32_t)(r * AS + pc * 8) * 2; \
        CP_ASYNC16(kb + off,               gKh + (size_t)((k0_) + r) * DH + pc * 8); \
        CP_ASYNC16(kb + KVARR_B + off,     gKl + (size_t)((k0_) + r) * DH + pc * 8); \
        CP_ASYNC16(kb + 2 * KVARR_B + off, gVh + (size_t)r * NS + (k0_) + pc * 8); \
    } \
    if (tid < 16) CP_ASYNC16(uMB + (s_) * 256 + tid * 16, mrow_g + (k0_) + tid * 4); \
} while (0)

    ATT_PREFETCH(0, 0);
    CP_COMMIT();

    // Stage Q hi tile through the (currently idle) buf1 area; pull A-fragments
    // into registers once.
    {
        __nv_bfloat16* Qtmp = sb + 3 * 64 * AS;
#pragma unroll
        for (int p = 0; p < 4; p++) {
            int f = tid + p * 128;
            int r = f >> 3, ln = (f & 7) * 8;
            *(uint4*)&Qtmp[r * AS + ln] = *(const uint4*)&gQh[(size_t)r * DH + ln];
        }
    }
    __syncthreads();
    uint32_t qf[4][4];
    {
        const uint32_t uQtmp = uS0 + (uint32_t)(3 * KVARR_B);
#pragma unroll
        for (int kk = 0; kk < 4; kk++)
            LDSM4(qf[kk], uQtmp + (uint32_t)((w * 16 + lrA) * AS + kk * 16 + hkA) * 2);
    }

    float oacc[8][4];
#pragma unroll
    for (int nt = 0; nt < 8; nt++)
#pragma unroll
        for (int e = 0; e < 4; e++) oacc[nt][e] = 0.0f;
    float m2[2] = {-1e30f, -1e30f}, l2[2] = {0.0f, 0.0f};
    const float scale2 = 0.125f * 1.4426950408889634f;   // scale * log2(e)
    const float M2C = 10000.0f * 1.4426950408889634f;    // mask coeff in log2

    for (int kt = 0; kt <= qi; kt++) {
        const int k0 = kt * 64;
        const int buf = kt & 1;
        __syncthreads();
        if (kt < qi) {
            ATT_PREFETCH(k0 + 64, buf ^ 1);
            CP_COMMIT();
            CP_WAIT(1);
        } else {
            CP_WAIT(0);
        }
        __syncthreads();

        const uint32_t uKh = uS0 + (uint32_t)(3 * buf) * KVARR_B;
        const uint32_t uKl = uKh + KVARR_B;
        const uint32_t uVh = uKh + 2 * KVARR_B;
        const float* mrow = mbuf + buf * 64;

        // ---- S = Qh @ K^T (2-term: Qh*Kh + Qh*Kl) ----
        float sacc[8][4];
#pragma unroll
        for (int nt = 0; nt < 8; nt++)
#pragma unroll
            for (int e = 0; e < 4; e++) sacc[nt][e] = 0.0f;
#pragma unroll
        for (int kk = 0; kk < 4; kk++) {
#pragma unroll
            for (int t2 = 0; t2 < 4; t2++) {
                uint32_t bh4[4], bl4[4];
                const uint32_t boff =
                    (uint32_t)((t2 * 16 + lrB) * AS + kk * 16 + hkB) * 2;
                LDSM4(bh4, uKh + boff);
                LDSM4(bl4, uKl + boff);
#pragma unroll
                for (int half = 0; half < 2; half++) {
                    const int nt = t2 * 2 + half;
                    MMA_BF16(sacc[nt], qf[kk], bh4[half * 2], bh4[half * 2 + 1]);
                    MMA_BF16(sacc[nt], qf[kk], bl4[half * 2], bl4[half * 2 + 1]);
                }
            }
        }

        // ---- softmax on fragments (log2 domain, diag-specialized) ----
        if (kt == qi) {
            SOFTMAX_BLOCK(1);
        } else {
            SOFTMAX_BLOCK(0);
        }

        // ---- O += P @ Vh: 2-term (Ph + Pl), P packed from registers ----
#pragma unroll
        for (int kk = 0; kk < 4; kk++) {
            uint32_t pah[4], pal[4];
            pah[0] = pack_hi_tr(sacc[2 * kk + 0][0], sacc[2 * kk + 0][1]);
            pah[1] = pack_hi_tr(sacc[2 * kk + 0][2], sacc[2 * kk + 0][3]);
            pah[2] = pack_hi_tr(sacc[2 * kk + 1][0], sacc[2 * kk + 1][1]);
            pah[3] = pack_hi_tr(sacc[2 * kk + 1][2], sacc[2 * kk + 1][3]);
            pal[0] = pack_lo_tr(sacc[2 * kk + 0][0], sacc[2 * kk + 0][1]);
            pal[1] = pack_lo_tr(sacc[2 * kk + 0][2], sacc[2 * kk + 0][3]);
            pal[2] = pack_lo_tr(sacc[2 * kk + 1][0], sacc[2 * kk + 1][1]);
            pal[3] = pack_lo_tr(sacc[2 * kk + 1][2], sacc[2 * kk + 1][3]);
#pragma unroll
            for (int t2 = 0; t2 < 4; t2++) {
                uint32_t bh4[4];
                const uint32_t boff =
                    (uint32_t)((t2 * 16 + lrB) * AS + kk * 16 + hkB) * 2;
                LDSM4(bh4, uVh + boff);
#pragma unroll
                for (int half = 0; half < 2; half++) {
                    const int nt = t2 * 2 + half;
                    MMA_BF16(oacc[nt], pah, bh4[half * 2], bh4[half * 2 + 1]);
                    MMA_BF16(oacc[nt], pal, bh4[half * 2], bh4[half * 2 + 1]);
                }
            }
        }
    }

    // normalize + merge heads
#pragma unroll
    for (int hi = 0; hi < 2; hi++) {
        const int row = q0 + w * 16 + rq + hi * 8;
        const float inv = 1.0f / l2[hi];
        float* orow = out + ((size_t)b * NS + row) * ND + h * DH;
#pragma unroll
        for (int nt = 0; nt < 8; nt++) {
            float2 o = make_float2(oacc[nt][hi * 2 + 0] * inv,
                                   oacc[nt][hi * 2 + 1] * inv);
            *(float2*)&orow[nt * 8 + cq] = o;
        }
    }
}

extern "C" void kernel_launch(void* const* d_in, const int* in_sizes, int n_in,
                              void* d_out, int out_size) {
    const float* hs   = (const float*)d_in[0];  // [B,S,D]
    const float* mask = (const float*)d_in[1];  // [B,S]
    const float* w    = (const float*)d_in[2];  // [D,3D]
    const float* bias = (const float*)d_in[3];  // [3D]

    float* out = (float*)d_out;
    float* kout = out + (size_t)NB * NS * ND;        // present[0] = K
    float* vout = kout + (size_t)NB * NH * NS * DH;  // present[1] = V

    cudaFuncSetAttribute(qkv_hmma_kernel,
                         cudaFuncAttributeMaxDynamicSharedMemorySize, GEMM_SMEM_B);
    cudaFuncSetAttribute(attn_hmma_kernel,
                         cudaFuncAttributeMaxDynamicSharedMemorySize, ATT_SMEM_B);

    // 1) bf16 hi/lo splits
    split_a_kernel<<<(MROWS * ND) / (256 * 4), 256>>>(hs);
    split_wt_kernel<<<dim3(N3 / 32, ND / 32), dim3(32, 8)>>>(w);
    // 2) HMMA QKV GEMM (BM=256, 3-stage pipeline, 1 barrier/stage)
    qkv_hmma_kernel<<<dim3(N3 / 128, MROWS / 256), 512, GEMM_SMEM_B>>>(
        bias, kout, vout);
    // 3) HMMA flash attention (unchanged)
    attn_hmma_kernel<<<dim3(NS / 64, NH, NB), 128, ATT_SMEM_B>>>(mask, out);
}

// round 17
// speedup vs baseline: 1.2751x; 1.1559x over previous
#include <cuda_runtime.h>
#include <cuda_bf16.h>
#include <cuda_fp16.h>
#include <cstdint>

#define NB 4
#define NS 2048
#define ND 1024
#define NH 16
#define DH 64
#define N3 3072
#define MROWS (NB * NS)  // 8192

// Device scratch (allocation-free)
__device__ __nv_bfloat16 g_ahi[(size_t)MROWS * ND];
__device__ __nv_bfloat16 g_alo[(size_t)MROWS * ND];
__device__ __nv_bfloat16 g_wthi[(size_t)N3 * ND];   // W^T hi [3072,1024]
__device__ __nv_bfloat16 g_wtlo[(size_t)N3 * ND];
__device__ __half g_qh[(size_t)NB * NH * NS * DH];   // Q fp16 [B,H,S,Dh]
__device__ __half g_kh[(size_t)NB * NH * NS * DH];   // K fp16 [B,H,S,Dh]
__device__ __half g_vth[(size_t)NB * NH * DH * NS];  // V^T fp16 [B,H,Dh,S]

// ---------------------------------------------------------------------------
// helpers
// ---------------------------------------------------------------------------
__device__ __forceinline__ uint32_t smem_u32(const void* p) {
    uint32_t a;
    asm("{ .reg .u64 t; cvta.to.shared.u64 t, %1; cvt.u32.u64 %0, t; }"
        : "=r"(a) : "l"(p));
    return a;
}
#define CP_ASYNC16(dst, src) \
    asm volatile("cp.async.cg.shared.global [%0], [%1], 16;" :: "r"(dst), "l"(src))
#define CP_COMMIT() asm volatile("cp.async.commit_group;" ::: "memory")
#define CP_WAIT(n)  asm volatile("cp.async.wait_group %0;" :: "n"(n) : "memory")
#define LDSM4(r, addr) asm volatile( \
    "ldmatrix.sync.aligned.m8n8.x4.shared.b16 {%0,%1,%2,%3}, [%4];" \
    : "=r"((r)[0]), "=r"((r)[1]), "=r"((r)[2]), "=r"((r)[3]) : "r"(addr))
#define MMA_BF16(c, a, b0, b1) asm volatile( \
    "mma.sync.aligned.m16n8k16.row.col.f32.bf16.bf16.f32 " \
    "{%0,%1,%2,%3}, {%4,%5,%6,%7}, {%8,%9}, {%0,%1,%2,%3};" \
    : "+f"((c)[0]), "+f"((c)[1]), "+f"((c)[2]), "+f"((c)[3]) \
    : "r"((a)[0]), "r"((a)[1]), "r"((a)[2]), "r"((a)[3]), "r"(b0), "r"(b1))
#define MMA_FP16(c, a, b0, b1) asm volatile( \
    "mma.sync.aligned.m16n8k16.row.col.f32.f16.f16.f32 " \
    "{%0,%1,%2,%3}, {%4,%5,%6,%7}, {%8,%9}, {%0,%1,%2,%3};" \
    : "+f"((c)[0]), "+f"((c)[1]), "+f"((c)[2]), "+f"((c)[3]) \
    : "r"((a)[0]), "r"((a)[1]), "r"((a)[2]), "r"((a)[3]), "r"(b0), "r"(b1))

__device__ __forceinline__ uint32_t packh2(float a, float b) {
    __half2 t = __floats2half2_rn(a, b);
    return *reinterpret_cast<uint32_t*>(&t);
}

// ---------------------------------------------------------------------------
// Prekernel: split A (fp32 -> bf16 hi + lo)
// ---------------------------------------------------------------------------
__global__ __launch_bounds__(256) void split_a_kernel(const float* __restrict__ A) {
    size_t i = ((size_t)blockIdx.x * 256 + threadIdx.x) * 4;
    float4 v = *(const float4*)(A + i);
    __nv_bfloat162 h01 = __floats2bfloat162_rn(v.x, v.y);
    __nv_bfloat162 h23 = __floats2bfloat162_rn(v.z, v.w);
    __nv_bfloat162 l01 = __floats2bfloat162_rn(v.x - __bfloat162float(h01.x),
                                               v.y - __bfloat162float(h01.y));
    __nv_bfloat162 l23 = __floats2bfloat162_rn(v.z - __bfloat162float(h23.x),
                                               v.w - __bfloat162float(h23.y));
    *(__nv_bfloat162*)(g_ahi + i)     = h01;
    *(__nv_bfloat162*)(g_ahi + i + 2) = h23;
    *(__nv_bfloat162*)(g_alo + i)     = l01;
    *(__nv_bfloat162*)(g_alo + i + 2) = l23;
}

// ---------------------------------------------------------------------------
// Prekernel: split + transpose W [1024,3072] -> Wt hi/lo [3072,1024]
// ---------------------------------------------------------------------------
__global__ __launch_bounds__(256) void split_wt_kernel(const float* __restrict__ W) {
    __shared__ float t[32][33];
    const int n0 = blockIdx.x * 32, k0 = blockIdx.y * 32;
    const int tx = threadIdx.x, ty = threadIdx.y;  // 32 x 8
#pragma unroll
    for (int j = 0; j < 4; j++)
        t[ty + j * 8][tx] = W[(size_t)(k0 + ty + j * 8) * N3 + n0 + tx];
    __syncthreads();
#pragma unroll
    for (int j = 0; j < 4; j++) {
        int n = n0 + ty + j * 8, k = k0 + tx;
        float v = t[tx][ty + j * 8];
        __nv_bfloat16 h = __float2bfloat16_rn(v);
        g_wthi[(size_t)n * ND + k] = h;
        g_wtlo[(size_t)n * ND + k] = __float2bfloat16_rn(v - __bfloat162float(h));
    }
}

// ---------------------------------------------------------------------------
// QKV GEMM on HMMA. CTA 256x128, 512 threads, 3-stage pipeline, 1 barrier/
// stage. K/V tiles 3-term bf16 split; Q tiles 2-term. Epilogue emits fp16
// Q, K, V^T for attention; fp32 K/V to present.
// ---------------------------------------------------------------------------
#define GST 40                      // bf16 smem stride
#define A_ARR_B (256 * GST * 2)     // 20480 B per A array
#define B_ARR_B (128 * GST * 2)     // 10240 B per B array
#define AH_OFF 0
#define AL_OFF A_ARR_B
#define BH_OFF (2 * A_ARR_B)
#define BL_OFF (2 * A_ARR_B + B_ARR_B)
#define STAGE_B (2 * A_ARR_B + 2 * B_ARR_B)   // 61440
#define NSTAGE 3
#define GEMM_SMEM_B (NSTAGE * STAGE_B)        // 184320
#define TST 264                     // V transpose staging stride (halfwords)

__global__ __launch_bounds__(512, 1) void qkv_hmma_kernel(
    const float* __restrict__ bias, float* __restrict__ kout, float* __restrict__ vout)
{
    extern __shared__ char gsm[];
    __shared__ float sbias[128];
    const uint32_t sb0 = smem_u32(gsm);
    const int tid = threadIdx.x;
    const int wid = tid >> 5, lane = tid & 31;
    const int wm = wid >> 1, wn = wid & 1;   // wm 0..7, wn 0..1
    const int m0 = blockIdx.y * 256, n0 = blockIdx.x * 128;
    const bool qt = (n0 < ND);      // Q-tile: 2-term, no A-lo

    if (tid < 128) sbias[tid] = bias[n0 + tid];

    const __nv_bfloat16* gAh = g_ahi + (size_t)m0 * ND;
    const __nv_bfloat16* gAl = g_alo + (size_t)m0 * ND;
    const __nv_bfloat16* gBh = g_wthi + (size_t)n0 * ND;
    const __nv_bfloat16* gBl = g_wtlo + (size_t)n0 * ND;

    const int r0g = tid >> 2, c0g = (tid & 3) * 8;

    float acc[2][8][4];
#pragma unroll
    for (int mt = 0; mt < 2; mt++)
#pragma unroll
        for (int nt = 0; nt < 8; nt++)
#pragma unroll
            for (int e = 0; e < 4; e++) acc[mt][nt][e] = 0.0f;

    const int lrA = lane & 15, hkA = (lane >> 4) * 8;
    const int lrB = (lane & 7) + ((lane >> 4) & 1) * 8;
    const int hkB = ((lane >> 3) & 1) * 8;

#define LOAD_STAGE(kc, buf) do { \
    uint32_t d = sb0 + (buf) * STAGE_B; \
    size_t ga0 = (size_t)r0g * ND + (kc) * 32 + c0g; \
    size_t ga1 = (size_t)(r0g + 128) * ND + (kc) * 32 + c0g; \
    uint32_t s0 = (uint32_t)(r0g * GST + c0g) * 2; \
    uint32_t s1 = (uint32_t)((r0g + 128) * GST + c0g) * 2; \
    CP_ASYNC16(d + AH_OFF + s0, gAh + ga0); \
    CP_ASYNC16(d + AH_OFF + s1, gAh + ga1); \
    if (!qt) { \
        CP_ASYNC16(d + AL_OFF + s0, gAl + ga0); \
        CP_ASYNC16(d + AL_OFF + s1, gAl + ga1); \
    } \
    CP_ASYNC16(d + BH_OFF + s0, gBh + ga0); \
    CP_ASYNC16(d + BL_OFF + s0, gBl + ga0); \
} while (0)

    LOAD_STAGE(0, 0);
    CP_COMMIT();
    LOAD_STAGE(1, 1);
    CP_COMMIT();

    for (int kc = 0; kc < ND / 32; kc++) {
        if (kc < ND / 32 - 1) {
            CP_WAIT(1);
        } else {
            CP_WAIT(0);
        }
        __syncthreads();

        const uint32_t sbuf = sb0 + (kc % 3) * STAGE_B;
#pragma unroll
        for (int kk = 0; kk < 2; kk++) {
            uint32_t ah[2][4], al[2][4];
#pragma unroll
            for (int mt = 0; mt < 2; mt++) {
                uint32_t a = sbuf +
                    (uint32_t)((wm * 32 + mt * 16 + lrA) * GST + kk * 16 + hkA) * 2;
                LDSM4(ah[mt], a + AH_OFF);
                if (!qt) LDSM4(al[mt], a + AL_OFF);
            }
#pragma unroll
            for (int nt2 = 0; nt2 < 4; nt2++) {
                uint32_t bh4[4], bl4[4];
                uint32_t a = sbuf +
                    (uint32_t)((wn * 64 + nt2 * 16 + lrB) * GST + kk * 16 + hkB) * 2;
                LDSM4(bh4, a + BH_OFF);
                LDSM4(bl4, a + BL_OFF);
#pragma unroll
                for (int mt = 0; mt < 2; mt++)
#pragma unroll
                    for (int half = 0; half < 2; half++) {
                        const int nt = nt2 * 2 + half;
                        MMA_BF16(acc[mt][nt], ah[mt], bh4[half * 2], bh4[half * 2 + 1]);
                        MMA_BF16(acc[mt][nt], ah[mt], bl4[half * 2], bl4[half * 2 + 1]);
                        if (!qt)
                            MMA_BF16(acc[mt][nt], al[mt], bh4[half * 2], bh4[half * 2 + 1]);
                    }
            }
        }

        if (kc + 2 < ND / 32) {
            LOAD_STAGE(kc + 2, (kc + 2) % 3);
            CP_COMMIT();
        }
    }

    // Epilogue
    const int sel = n0 >> 10;
    const int rl = lane >> 2, cpair = (lane & 3) * 2;
    __half* T = (__half*)gsm;  // transpose staging (sel==2 only)
    __syncthreads();  // all compute done before reusing gsm as staging
#pragma unroll
    for (int mt = 0; mt < 2; mt++) {
#pragma unroll
        for (int half = 0; half < 2; half++) {
            const int mloc = wm * 32 + mt * 16 + rl + half * 8;
            const int m = m0 + mloc;
            const int b = m >> 11, s = m & (NS - 1);
#pragma unroll
            for (int nt = 0; nt < 8; nt++) {
                const int coln = wn * 64 + nt * 8 + cpair;
                const int h = ((n0 & (ND - 1)) >> 6) + (coln >> 6);
                const int d = coln & 63;
                const float v0 = acc[mt][nt][half * 2 + 0] + sbias[coln];
                const float v1 = acc[mt][nt][half * 2 + 1] + sbias[coln + 1];
                const size_t idx = (((size_t)b * NH + h) * NS + s) * DH + d;
                __half2 hh = __floats2half2_rn(v0, v1);
                if (sel == 0) {
                    *(__half2*)&g_qh[idx] = hh;
                } else if (sel == 1) {
                    *(float2*)&kout[idx] = make_float2(v0, v1);
                    *(__half2*)&g_kh[idx] = hh;
                } else {
                    *(float2*)&vout[idx] = make_float2(v0, v1);
                    T[coln * TST + mloc] = __low2half(hh);
                    T[(coln + 1) * TST + mloc] = __high2half(hh);
                }
            }
        }
    }
    if (sel == 2) {
        __syncthreads();  // CTA-uniform condition; legal
        const int b2 = m0 >> 11, s0g = m0 & (NS - 1);
        const int hb = (n0 & (ND - 1)) >> 6;
#pragma unroll
        for (int p = 0; p < 8; p++) {
            const int idx = tid + p * 512;
            const int n = idx >> 5, c8 = (idx & 31) * 8;
            uint4 v = *(uint4*)&T[n * TST + c8];
            const int h2 = hb + (n >> 6);
            const int d = n & 63;
            *(uint4*)&g_vth[(((size_t)b2 * NH + h2) * DH + d) * NS + s0g + c8] = v;
        }
    }
}

// ---------------------------------------------------------------------------
// Flash attention on fp16 HMMA: single-term QK^T and PV (fp16 precision is
// below the existing error floor at these magnitudes). FA2 register-P,
// register-Q, cp.async double-buffered K/V, log2-domain softmax.
// smem: 2 stages x {K, V} fp16 (9216 B each) + mask = 37.4 KB.
// ---------------------------------------------------------------------------
#define AS 72                       // fp16 smem stride
#define KVARR_B (64 * AS * 2)       // 9216 B per array
#define ATT_SMEM_B (4 * KVARR_B + 512)

#define SOFTMAX_BLOCK(DIAGC) do { \
    _Pragma("unroll") \
    for (int hi = 0; hi < 2; hi++) { \
        const int row = q0 + w * 16 + rq + hi * 8; \
        float mx = -1e30f; \
        _Pragma("unroll") \
        for (int nt = 0; nt < 8; nt++) { \
            float v0 = fmaf(sacc[nt][hi * 2 + 0], scale2, \
                            fmaf(mrow[nt * 8 + cq], M2C, -M2C)); \
            float v1 = fmaf(sacc[nt][hi * 2 + 1], scale2, \
                            fmaf(mrow[nt * 8 + cq + 1], M2C, -M2C)); \
            if (DIAGC && (k0 + nt * 8 + cq + 0 > row)) v0 = -1e30f; \
            if (DIAGC && (k0 + nt * 8 + cq + 1 > row)) v1 = -1e30f; \
            sacc[nt][hi * 2 + 0] = v0; \
            sacc[nt][hi * 2 + 1] = v1; \
            mx = fmaxf(mx, fmaxf(v0, v1)); \
        } \
        mx = fmaxf(mx, __shfl_xor_sync(0xffffffffu, mx, 1)); \
        mx = fmaxf(mx, __shfl_xor_sync(0xffffffffu, mx, 2)); \
        const float mn = fmaxf(m2[hi], mx); \
        const float alpha = exp2f(m2[hi] - mn); \
        m2[hi] = mn; \
        float ps = 0.0f; \
        _Pragma("unroll") \
        for (int nt = 0; nt < 8; nt++) { \
            float p0 = exp2f(sacc[nt][hi * 2 + 0] - mn); \
            float p1 = exp2f(sacc[nt][hi * 2 + 1] - mn); \
            sacc[nt][hi * 2 + 0] = p0; \
            sacc[nt][hi * 2 + 1] = p1; \
            ps += p0 + p1; \
        } \
        ps += __shfl_xor_sync(0xffffffffu, ps, 1); \
        ps += __shfl_xor_sync(0xffffffffu, ps, 2); \
        l2[hi] = l2[hi] * alpha + ps; \
        _Pragma("unroll") \
        for (int nt = 0; nt < 8; nt++) { \
            oacc[nt][hi * 2 + 0] *= alpha; \
            oacc[nt][hi * 2 + 1] *= alpha; \
        } \
    } \
} while (0)

__global__ __launch_bounds__(128, 4) void attn_hmma_kernel(
    const float* __restrict__ mask, float* __restrict__ out)
{
    extern __shared__ __half sh[];
    float* mbuf = (float*)(sh + 4 * 64 * AS);  // raw mask, 2 x 64 floats

    const int tid = threadIdx.x;
    const int w = tid >> 5, lane = tid & 31;
    const int qi = (gridDim.x - 1) - blockIdx.x;  // long blocks first
    const int h = blockIdx.y, b = blockIdx.z;
    const int q0 = qi * 64;
    const size_t hoff = (((size_t)b * NH + h) * NS) * DH;
    const __half* gQh = g_qh + hoff + (size_t)q0 * DH;
    const __half* gKh = g_kh + hoff;
    const size_t voff = (((size_t)b * NH + h) * DH) * NS;
    const __half* gVh = g_vth + voff;
    const float* mrow_g = mask + (size_t)b * NS;

    const uint32_t uS0 = smem_u32(sh);
    const uint32_t uMB = smem_u32(mbuf);

    const int lrA = lane & 15, hkA = (lane >> 4) * 8;
    const int lrB = (lane & 7) + ((lane >> 4) & 1) * 8;
    const int hkB = ((lane >> 3) & 1) * 8;
    const int rq = lane >> 2, cq = (lane & 3) * 2;

    const int pr = tid >> 3;            // base row (+16 per p)
    const int pc = (tid & 7);           // 16B line within 128B row

#define ATT_PREFETCH(k0_, s_) do { \
    uint32_t kb = uS0 + (uint32_t)(2 * (s_)) * KVARR_B; \
    _Pragma("unroll") \
    for (int p = 0; p < 4; p++) { \
        int r = pr + p * 16; \
        uint32_t off = (uint32_t)(r * AS + pc * 8) * 2; \
        CP_ASYNC16(kb + off,           gKh + (size_t)((k0_) + r) * DH + pc * 8); \
        CP_ASYNC16(kb + KVARR_B + off, gVh + (size_t)r * NS + (k0_) + pc * 8); \
    } \
    if (tid < 16) CP_ASYNC16(uMB + (s_) * 256 + tid * 16, mrow_g + (k0_) + tid * 4); \
} while (0)

    ATT_PREFETCH(0, 0);
    CP_COMMIT();

    // Stage Q tile through the (currently idle) stage-1 K area; pull
    // A-fragments into registers once.
    {
        __half* Qtmp = sh + 2 * 64 * AS;
#pragma unroll
        for (int p = 0; p < 4; p++) {
            int f = tid + p * 128;
            int r = f >> 3, ln = (f & 7) * 8;
            *(uint4*)&Qtmp[r * AS + ln] = *(const uint4*)&gQh[(size_t)r * DH + ln];
        }
    }
    __syncthreads();
    uint32_t qf[4][4];
    {
        const uint32_t uQtmp = uS0 + (uint32_t)(2 * KVARR_B);
#pragma unroll
        for (int kk = 0; kk < 4; kk++)
            LDSM4(qf[kk], uQtmp + (uint32_t)((w * 16 + lrA) * AS + kk * 16 + hkA) * 2);
    }

    float oacc[8][4];
#pragma unroll
    for (int nt = 0; nt < 8; nt++)
#pragma unroll
        for (int e = 0; e < 4; e++) oacc[nt][e] = 0.0f;
    float m2[2] = {-1e30f, -1e30f}, l2[2] = {0.0f, 0.0f};
    const float scale2 = 0.125f * 1.4426950408889634f;   // scale * log2(e)
    const float M2C = 10000.0f * 1.4426950408889634f;    // mask coeff in log2

    for (int kt = 0; kt <= qi; kt++) {
        const int k0 = kt * 64;
        const int buf = kt & 1;
        __syncthreads();
        if (kt < qi) {
            ATT_PREFETCH(k0 + 64, buf ^ 1);
            CP_COMMIT();
            CP_WAIT(1);
        } else {
            CP_WAIT(0);
        }
        __syncthreads();

        const uint32_t uKh = uS0 + (uint32_t)(2 * buf) * KVARR_B;
        const uint32_t uVh = uKh + KVARR_B;
        const float* mrow = mbuf + buf * 64;

        // ---- S = Q @ K^T (single fp16 term) ----
        float sacc[8][4];
#pragma unroll
        for (int nt = 0; nt < 8; nt++)
#pragma unroll
            for (int e = 0; e < 4; e++) sacc[nt][e] = 0.0f;
#pragma unroll
        for (int kk = 0; kk < 4; kk++) {
#pragma unroll
            for (int t2 = 0; t2 < 4; t2++) {
                uint32_t bh4[4];
                const uint32_t boff =
                    (uint32_t)((t2 * 16 + lrB) * AS + kk * 16 + hkB) * 2;
                LDSM4(bh4, uKh + boff);
#pragma unroll
                for (int half = 0; half < 2; half++) {
                    const int nt = t2 * 2 + half;
                    MMA_FP16(sacc[nt], qf[kk], bh4[half * 2], bh4[half * 2 + 1]);
                }
            }
        }

        // ---- softmax on fragments (log2 domain, diag-specialized) ----
        if (kt == qi) {
            SOFTMAX_BLOCK(1);
        } else {
            SOFTMAX_BLOCK(0);
        }

        // ---- O += P @ V (single fp16 term, P packed from registers) ----
#pragma unroll
        for (int kk = 0; kk < 4; kk++) {
            uint32_t pah[4];
            pah[0] = packh2(sacc[2 * kk + 0][0], sacc[2 * kk + 0][1]);
            pah[1] = packh2(sacc[2 * kk + 0][2], sacc[2 * kk + 0][3]);
            pah[2] = packh2(sacc[2 * kk + 1][0], sacc[2 * kk + 1][1]);
            pah[3] = packh2(sacc[2 * kk + 1][2], sacc[2 * kk + 1][3]);
#pragma unroll
            for (int t2 = 0; t2 < 4; t2++) {
                uint32_t bh4[4];
                const uint32_t boff =
                    (uint32_t)((t2 * 16 + lrB) * AS + kk * 16 + hkB) * 2;
                LDSM4(bh4, uVh + boff);
#pragma unroll
                for (int half = 0; half < 2; half++) {
                    const int nt = t2 * 2 + half;
                    MMA_FP16(oacc[nt], pah, bh4[half * 2], bh4[half * 2 + 1]);
                }
            }
        }
    }

    // normalize + merge heads
#pragma unroll
    for (int hi = 0; hi < 2; hi++) {
        const int row = q0 + w * 16 + rq + hi * 8;
        const float inv = 1.0f / l2[hi];
        float* orow = out + ((size_t)b * NS + row) * ND + h * DH;
#pragma unroll
        for (int nt = 0; nt < 8; nt++) {
            float2 o = make_float2(oacc[nt][hi * 2 + 0] * inv,
                                   oacc[nt][hi * 2 + 1] * inv);
            *(float2*)&orow[nt * 8 + cq] = o;
        }
    }
}

extern "C" void kernel_launch(void* const* d_in, const int* in_sizes, int n_in,
                              void* d_out, int out_size) {
    const float* hs   = (const float*)d_in[0];  // [B,S,D]
    const float* mask = (const float*)d_in[1];  // [B,S]
    const float* w    = (const float*)d_in[2];  // [D,3D]
    const float* bias = (const float*)d_in[3];  // [3D]

    float* out = (float*)d_out;
    float* kout = out + (size_t)NB * NS * ND;        // present[0] = K
    float* vout = kout + (size_t)NB * NH * NS * DH;  // present[1] = V

    cudaFuncSetAttribute(qkv_hmma_kernel,
                         cudaFuncAttributeMaxDynamicSharedMemorySize, GEMM_SMEM_B);
    cudaFuncSetAttribute(attn_hmma_kernel,
                         cudaFuncAttributeMaxDynamicSharedMemorySize, ATT_SMEM_B);

    // 1) bf16 hi/lo splits
    split_a_kernel<<<(MROWS * ND) / (256 * 4), 256>>>(hs);
    split_wt_kernel<<<dim3(N3 / 32, ND / 32), dim3(32, 8)>>>(w);
    // 2) HMMA QKV GEMM (BM=256, 3-stage; fp16 Q/K/V^T emission)
    qkv_hmma_kernel<<<dim3(N3 / 128, MROWS / 256), 512, GEMM_SMEM_B>>>(
        bias, kout, vout);
    // 3) fp16 HMMA flash attention (single-term QK^T and PV)
    attn_hmma_kernel<<<dim3(NS / 64, NH, NB), 128, ATT_SMEM_B>>>(mask, out);
}